// round 1
// baseline (speedup 1.0000x reference)
#include <cuda_runtime.h>
#include <math.h>

// Problem constants (fixed by the reference setup)
#define BATCH 4
#define NPTS  4096
#define DIM   64
#define SIGMA 0.05f
#define LOG2E 1.4426950408889634f
// SC = sqrt(LOG2E)/SIGMA  -> SC^2 = LOG2E/SIGMA^2 = 577.07802
#define SC_F  24.0224478f

#define BM 64            // i-rows per CTA
#define BN 64            // j-cols per tile
#define STR 68           // padded stride (floats) for [d][j] transposed tiles
#define NTILES (NPTS/BN) // 64
#define ITILES (NPTS/BM) // 64

// Scratch (no allocations allowed)
__device__ float g_Ln1[BATCH*NPTS];           // log2e * ||f1_i||^2
__device__ float g_Ln2[BATCH*NPTS];           // log2e * ||f2_j||^2
__device__ float g_partial[BATCH*ITILES];     // per (b, i-tile) partial loss

__device__ __forceinline__ float ex2(float x){
    float y;
    asm("ex2.approx.ftz.f32 %0, %1;" : "=f"(y) : "f"(x));
    return y;
}

// ---------------------------------------------------------------------------
// Kernel 1: per-row feature norms (scaled by log2e). One warp per row.
// ---------------------------------------------------------------------------
__global__ void norms_kernel(const float* __restrict__ f1,
                             const float* __restrict__ f2)
{
    int gw   = (blockIdx.x * blockDim.x + threadIdx.x) >> 5;
    int lane = threadIdx.x & 31;
    if (gw >= BATCH*NPTS) return;
    const float* r1 = f1 + (size_t)gw * DIM;
    const float* r2 = f2 + (size_t)gw * DIM;
    float a0 = r1[lane], a1 = r1[lane + 32];
    float s1 = a0*a0 + a1*a1;
    float b0 = r2[lane], b1 = r2[lane + 32];
    float s2 = b0*b0 + b1*b1;
    #pragma unroll
    for (int off = 16; off >= 1; off >>= 1){
        s1 += __shfl_xor_sync(0xffffffffu, s1, off);
        s2 += __shfl_xor_sync(0xffffffffu, s2, off);
    }
    if (lane == 0){
        g_Ln1[gw] = s1 * LOG2E;
        g_Ln2[gw] = s2 * LOG2E;
    }
}

// ---------------------------------------------------------------------------
// Kernel 2: fused single-pass dual online-softmax squared-difference loss.
// CTA: 256 threads = 16x16, handles BM=64 rows of one batch.
// Thread (ty,tx): rows ty*4..+3, cols tx*4..+3 of each 64x64 j-tile.
// Per-thread online state per row: m1,m2,Z1,Z2,A,B,C over its own j-subset;
// merged across the 16 tx-lanes at the end (log-sum-exp state merge).
// ---------------------------------------------------------------------------
__global__ __launch_bounds__(256, 2)
void loss_kernel(const float* __restrict__ pts,
                 const float* __restrict__ wts,
                 const float* __restrict__ f1,
                 const float* __restrict__ f2)
{
    __shared__ __align__(16) float f1T[DIM*STR];   // [d][i], f1 * 2*log2e
    __shared__ __align__(16) float f2T[DIM*STR];   // [d][j], raw
    __shared__ __align__(16) float p2T[3*STR];     // [c][j], pts * SC
    __shared__ float Ln2s[BN];
    __shared__ float sred[16];

    const int b   = blockIdx.y;
    const int i0  = blockIdx.x * BM;
    const int tid = threadIdx.x;
    const int tx  = tid & 15;
    const int ty  = tid >> 4;

    // ---- load f1 tile transposed (global read already j-major so STS is
    //      lane-consecutive -> conflict-free), scaled by 2*log2e ----
    {
        int i   = tid & 63;
        int seg = tid >> 6;                 // 0..3 -> 16 d each
        const float* src = f1 + ((size_t)(b*NPTS + i0 + i))*DIM + seg*16;
        #pragma unroll
        for (int q4 = 0; q4 < 4; q4++){
            float4 v = *(const float4*)(src + q4*4);
            int d0 = seg*16 + q4*4;
            f1T[(d0+0)*STR + i] = v.x * (2.0f*LOG2E);
            f1T[(d0+1)*STR + i] = v.y * (2.0f*LOG2E);
            f1T[(d0+2)*STR + i] = v.z * (2.0f*LOG2E);
            f1T[(d0+3)*STR + i] = v.w * (2.0f*LOG2E);
        }
    }

    // ---- per-thread row constants ----
    float xi[4][3];      // scaled coordinates of my 4 rows
    float Ln1r[4];       // log2e * ||f1_i||^2
    #pragma unroll
    for (int r = 0; r < 4; r++){
        int row = b*NPTS + i0 + ty*4 + r;
        xi[r][0] = pts[(size_t)row*3 + 0] * SC_F;
        xi[r][1] = pts[(size_t)row*3 + 1] * SC_F;
        xi[r][2] = pts[(size_t)row*3 + 2] * SC_F;
        Ln1r[r]  = g_Ln1[row];
    }

    // ---- online-softmax state ----
    float m1[4], m2[4], Z1[4], Z2[4], Aa[4], Bb[4], Cc[4];
    #pragma unroll
    for (int r = 0; r < 4; r++){
        m1[r] = -3.0e38f; m2[r] = -3.0e38f;
        Z1[r] = 0.f; Z2[r] = 0.f; Aa[r] = 0.f; Bb[r] = 0.f; Cc[r] = 0.f;
    }

    for (int jt = 0; jt < NTILES; jt++){
        const int j0 = jt * BN;
        __syncthreads();
        // load f2 tile transposed (raw)
        {
            int j   = tid & 63;
            int seg = tid >> 6;
            const float* src = f2 + ((size_t)(b*NPTS + j0 + j))*DIM + seg*16;
            #pragma unroll
            for (int q4 = 0; q4 < 4; q4++){
                float4 v = *(const float4*)(src + q4*4);
                int d0 = seg*16 + q4*4;
                f2T[(d0+0)*STR + j] = v.x;
                f2T[(d0+1)*STR + j] = v.y;
                f2T[(d0+2)*STR + j] = v.z;
                f2T[(d0+3)*STR + j] = v.w;
            }
        }
        if (tid < 192){
            int j = tid & 63, c = tid >> 6;
            p2T[c*STR + j] = pts[((size_t)(b*NPTS + j0 + j))*3 + c] * SC_F;
        }
        if (tid < 64) Ln2s[tid] = g_Ln2[b*NPTS + j0 + tid];
        __syncthreads();

        // init feature-score accumulators with -(Ln1_i + Ln2_j)
        float acc[4][4];
        float4 cn2 = *(const float4*)&Ln2s[tx*4];
        #pragma unroll
        for (int r = 0; r < 4; r++){
            acc[r][0] = -(Ln1r[r] + cn2.x);
            acc[r][1] = -(Ln1r[r] + cn2.y);
            acc[r][2] = -(Ln1r[r] + cn2.z);
            acc[r][3] = -(Ln1r[r] + cn2.w);
        }

        // feature GEMM: acc += (2*log2e*f1_i) . f2_j
        #pragma unroll 16
        for (int k = 0; k < DIM; k++){
            float4 a4 = *(const float4*)&f1T[k*STR + ty*4];
            float4 b4 = *(const float4*)&f2T[k*STR + tx*4];
            acc[0][0] += a4.x*b4.x; acc[0][1] += a4.x*b4.y;
            acc[0][2] += a4.x*b4.z; acc[0][3] += a4.x*b4.w;
            acc[1][0] += a4.y*b4.x; acc[1][1] += a4.y*b4.y;
            acc[1][2] += a4.y*b4.z; acc[1][3] += a4.y*b4.w;
            acc[2][0] += a4.z*b4.x; acc[2][1] += a4.z*b4.y;
            acc[2][2] += a4.z*b4.z; acc[2][3] += a4.z*b4.w;
            acc[3][0] += a4.w*b4.x; acc[3][1] += a4.w*b4.y;
            acc[3][2] += a4.w*b4.z; acc[3][3] += a4.w*b4.w;
        }

        // spatial coordinates of my 4 cols
        float xj[3][4];
        #pragma unroll
        for (int c = 0; c < 3; c++){
            float4 v = *(const float4*)&p2T[c*STR + tx*4];
            xj[c][0] = v.x; xj[c][1] = v.y; xj[c][2] = v.z; xj[c][3] = v.w;
        }

        // epilogue: per-row online update (one rescale per tile per row)
        #pragma unroll
        for (int r = 0; r < 4; r++){
            float s1v[4], s2v[4];
            #pragma unroll
            for (int q = 0; q < 4; q++){
                s2v[q] = fminf(acc[r][q], 0.0f);       // clamp d2 >= 0
                float t0 = xi[r][0] - xj[0][q];
                float t1 = xi[r][1] - xj[1][q];
                float t2 = xi[r][2] - xj[2][q];
                s1v[q] = -(t0*t0 + t1*t1 + t2*t2);     // exact >= 0 distance
            }
            float tm1 = fmaxf(fmaxf(s1v[0], s1v[1]), fmaxf(s1v[2], s1v[3]));
            float tm2 = fmaxf(fmaxf(s2v[0], s2v[1]), fmaxf(s2v[2], s2v[3]));
            float m1n = fmaxf(m1[r], tm1);
            float m2n = fmaxf(m2[r], tm2);
            float c1 = ex2(m1[r] - m1n);
            float c2 = ex2(m2[r] - m2n);
            float e1[4], e2[4];
            #pragma unroll
            for (int q = 0; q < 4; q++){
                e1[q] = ex2(s1v[q] - m1n);
                e2[q] = ex2(s2v[q] - m2n);
            }
            float sZ1 = (e1[0]+e1[1]) + (e1[2]+e1[3]);
            float sZ2 = (e2[0]+e2[1]) + (e2[2]+e2[3]);
            float sA  = (e1[0]*e1[0]+e1[1]*e1[1]) + (e1[2]*e1[2]+e1[3]*e1[3]);
            float sB  = (e2[0]*e2[0]+e2[1]*e2[1]) + (e2[2]*e2[2]+e2[3]*e2[3]);
            float sC  = (e1[0]*e2[0]+e1[1]*e2[1]) + (e1[2]*e2[2]+e1[3]*e2[3]);
            Z1[r] = Z1[r]*c1        + sZ1;
            Aa[r] = Aa[r]*(c1*c1)   + sA;
            Z2[r] = Z2[r]*c2        + sZ2;
            Bb[r] = Bb[r]*(c2*c2)   + sB;
            Cc[r] = Cc[r]*(c1*c2)   + sC;
            m1[r] = m1n; m2[r] = m2n;
        }
    }

    // ---- merge the 16 tx-lane partial states per row ----
    #pragma unroll
    for (int r = 0; r < 4; r++){
        #pragma unroll
        for (int off = 8; off >= 1; off >>= 1){
            float om1 = __shfl_xor_sync(0xffffffffu, m1[r], off);
            float om2 = __shfl_xor_sync(0xffffffffu, m2[r], off);
            float oZ1 = __shfl_xor_sync(0xffffffffu, Z1[r], off);
            float oZ2 = __shfl_xor_sync(0xffffffffu, Z2[r], off);
            float oA  = __shfl_xor_sync(0xffffffffu, Aa[r], off);
            float oB  = __shfl_xor_sync(0xffffffffu, Bb[r], off);
            float oC  = __shfl_xor_sync(0xffffffffu, Cc[r], off);
            float nm1 = fmaxf(m1[r], om1);
            float nm2 = fmaxf(m2[r], om2);
            float c1 = ex2(m1[r] - nm1), d1 = ex2(om1 - nm1);
            float c2 = ex2(m2[r] - nm2), d2 = ex2(om2 - nm2);
            Z1[r] = Z1[r]*c1      + oZ1*d1;
            Aa[r] = Aa[r]*c1*c1   + oA*d1*d1;
            Z2[r] = Z2[r]*c2      + oZ2*d2;
            Bb[r] = Bb[r]*c2*c2   + oB*d2*d2;
            Cc[r] = Cc[r]*(c1*c2) + oC*(d1*d2);
            m1[r] = nm1; m2[r] = nm2;
        }
    }

    // ---- loss per row, weighted sum over CTA ----
    if (tx == 0){
        float wacc = 0.0f;
        #pragma unroll
        for (int r = 0; r < 4; r++){
            float i1 = 1.0f / Z1[r];
            float i2 = 1.0f / Z2[r];
            float loss = Aa[r]*i1*i1 - 2.0f*Cc[r]*i1*i2 + Bb[r]*i2*i2;
            wacc += wts[b*NPTS + i0 + ty*4 + r] * loss;
        }
        sred[ty] = wacc;
    }
    __syncthreads();
    if (tid == 0){
        float s = 0.0f;
        #pragma unroll
        for (int t = 0; t < 16; t++) s += sred[t];
        g_partial[b*ITILES + blockIdx.x] = s;
    }
}

// ---------------------------------------------------------------------------
// Kernel 3: deterministic final reduction (64 partials per batch)
// ---------------------------------------------------------------------------
__global__ void reduce_kernel(float* __restrict__ out)
{
    int b    = threadIdx.x >> 5;    // 4 warps, one per batch
    int lane = threadIdx.x & 31;
    float s = g_partial[b*ITILES + lane] + g_partial[b*ITILES + 32 + lane];
    #pragma unroll
    for (int off = 16; off >= 1; off >>= 1)
        s += __shfl_xor_sync(0xffffffffu, s, off);
    if (lane == 0) out[b] = s;
}

// ---------------------------------------------------------------------------
extern "C" void kernel_launch(void* const* d_in, const int* in_sizes, int n_in,
                              void* d_out, int out_size)
{
    const float* pts = (const float*)d_in[0];  // [4,4096,3]
    const float* wts = (const float*)d_in[1];  // [4,4096]
    const float* f1  = (const float*)d_in[2];  // [4,4096,64]
    const float* f2  = (const float*)d_in[3];  // [4,4096,64]
    float* out = (float*)d_out;                // [4]

    norms_kernel<<<(BATCH*NPTS)/8, 256>>>(f1, f2);
    dim3 grid(ITILES, BATCH);
    loss_kernel<<<grid, 256>>>(pts, wts, f1, f2);
    reduce_kernel<<<1, 128>>>(out);
}

// round 2
// speedup vs baseline: 1.0007x; 1.0007x over previous
#include <cuda_runtime.h>
#include <math.h>

// Problem constants (fixed by the reference setup)
#define BATCH 4
#define NPTS  4096
#define DIM   64
#define SIGMA 0.05f
#define LOG2E 1.4426950408889634f
// SC = sqrt(LOG2E)/SIGMA  -> SC^2 = LOG2E/SIGMA^2 = 577.07802
#define SC_F  24.0224478f

#define BM 64            // i-rows per CTA
#define BN 64            // j-cols per tile
#define STR 68           // padded stride (floats) for [d][j] transposed tiles
#define NTILES (NPTS/BN) // 64
#define ITILES (NPTS/BM) // 64

// Scratch (no allocations allowed)
__device__ float g_Ln1[BATCH*NPTS];           // log2e * ||f1_i||^2
__device__ float g_Ln2[BATCH*NPTS];           // log2e * ||f2_j||^2
__device__ float g_partial[BATCH*ITILES];     // per (b, i-tile) partial loss

__device__ __forceinline__ float ex2(float x){
    float y;
    asm("ex2.approx.ftz.f32 %0, %1;" : "=f"(y) : "f"(x));
    return y;
}

// ---------------------------------------------------------------------------
// Kernel 1: per-row feature norms (scaled by log2e). One warp per row.
// ---------------------------------------------------------------------------
__global__ void norms_kernel(const float* __restrict__ f1,
                             const float* __restrict__ f2)
{
    int gw   = (blockIdx.x * blockDim.x + threadIdx.x) >> 5;
    int lane = threadIdx.x & 31;
    if (gw >= BATCH*NPTS) return;
    const float* r1 = f1 + (size_t)gw * DIM;
    const float* r2 = f2 + (size_t)gw * DIM;
    float a0 = r1[lane], a1 = r1[lane + 32];
    float s1 = a0*a0 + a1*a1;
    float b0 = r2[lane], b1 = r2[lane + 32];
    float s2 = b0*b0 + b1*b1;
    #pragma unroll
    for (int off = 16; off >= 1; off >>= 1){
        s1 += __shfl_xor_sync(0xffffffffu, s1, off);
        s2 += __shfl_xor_sync(0xffffffffu, s2, off);
    }
    if (lane == 0){
        g_Ln1[gw] = s1 * LOG2E;
        g_Ln2[gw] = s2 * LOG2E;
    }
}

// ---------------------------------------------------------------------------
// Kernel 2: fused single-pass dual online-softmax squared-difference loss.
// CTA: 256 threads = 16x16, handles BM=64 rows of one batch.
// Thread (ty,tx): rows ty*4..+3, cols tx*4..+3 of each 64x64 j-tile.
// Per-thread online state per row: m1,m2,Z1,Z2,A,B,C over its own j-subset;
// merged across the 16 tx-lanes at the end (log-sum-exp state merge).
// ---------------------------------------------------------------------------
__global__ __launch_bounds__(256, 2)
void loss_kernel(const float* __restrict__ pts,
                 const float* __restrict__ wts,
                 const float* __restrict__ f1,
                 const float* __restrict__ f2)
{
    __shared__ __align__(16) float f1T[DIM*STR];   // [d][i], f1 * 2*log2e
    __shared__ __align__(16) float f2T[DIM*STR];   // [d][j], raw
    __shared__ __align__(16) float p2T[3*STR];     // [c][j], pts * SC
    __shared__ float Ln2s[BN];
    __shared__ float sred[16];

    const int b   = blockIdx.y;
    const int i0  = blockIdx.x * BM;
    const int tid = threadIdx.x;
    const int tx  = tid & 15;
    const int ty  = tid >> 4;

    // ---- load f1 tile transposed (global read already j-major so STS is
    //      lane-consecutive -> conflict-free), scaled by 2*log2e ----
    {
        int i   = tid & 63;
        int seg = tid >> 6;                 // 0..3 -> 16 d each
        const float* src = f1 + ((size_t)(b*NPTS + i0 + i))*DIM + seg*16;
        #pragma unroll
        for (int q4 = 0; q4 < 4; q4++){
            float4 v = *(const float4*)(src + q4*4);
            int d0 = seg*16 + q4*4;
            f1T[(d0+0)*STR + i] = v.x * (2.0f*LOG2E);
            f1T[(d0+1)*STR + i] = v.y * (2.0f*LOG2E);
            f1T[(d0+2)*STR + i] = v.z * (2.0f*LOG2E);
            f1T[(d0+3)*STR + i] = v.w * (2.0f*LOG2E);
        }
    }

    // ---- per-thread row constants ----
    float xi[4][3];      // scaled coordinates of my 4 rows
    float Ln1r[4];       // log2e * ||f1_i||^2
    #pragma unroll
    for (int r = 0; r < 4; r++){
        int row = b*NPTS + i0 + ty*4 + r;
        xi[r][0] = pts[(size_t)row*3 + 0] * SC_F;
        xi[r][1] = pts[(size_t)row*3 + 1] * SC_F;
        xi[r][2] = pts[(size_t)row*3 + 2] * SC_F;
        Ln1r[r]  = g_Ln1[row];
    }

    // ---- online-softmax state ----
    float m1[4], m2[4], Z1[4], Z2[4], Aa[4], Bb[4], Cc[4];
    #pragma unroll
    for (int r = 0; r < 4; r++){
        m1[r] = -3.0e38f; m2[r] = -3.0e38f;
        Z1[r] = 0.f; Z2[r] = 0.f; Aa[r] = 0.f; Bb[r] = 0.f; Cc[r] = 0.f;
    }

    for (int jt = 0; jt < NTILES; jt++){
        const int j0 = jt * BN;
        __syncthreads();
        // load f2 tile transposed (raw)
        {
            int j   = tid & 63;
            int seg = tid >> 6;
            const float* src = f2 + ((size_t)(b*NPTS + j0 + j))*DIM + seg*16;
            #pragma unroll
            for (int q4 = 0; q4 < 4; q4++){
                float4 v = *(const float4*)(src + q4*4);
                int d0 = seg*16 + q4*4;
                f2T[(d0+0)*STR + j] = v.x;
                f2T[(d0+1)*STR + j] = v.y;
                f2T[(d0+2)*STR + j] = v.z;
                f2T[(d0+3)*STR + j] = v.w;
            }
        }
        if (tid < 192){
            int j = tid & 63, c = tid >> 6;
            p2T[c*STR + j] = pts[((size_t)(b*NPTS + j0 + j))*3 + c] * SC_F;
        }
        if (tid < 64) Ln2s[tid] = g_Ln2[b*NPTS + j0 + tid];
        __syncthreads();

        // init feature-score accumulators with -(Ln1_i + Ln2_j)
        float acc[4][4];
        float4 cn2 = *(const float4*)&Ln2s[tx*4];
        #pragma unroll
        for (int r = 0; r < 4; r++){
            acc[r][0] = -(Ln1r[r] + cn2.x);
            acc[r][1] = -(Ln1r[r] + cn2.y);
            acc[r][2] = -(Ln1r[r] + cn2.z);
            acc[r][3] = -(Ln1r[r] + cn2.w);
        }

        // feature GEMM: acc += (2*log2e*f1_i) . f2_j
        #pragma unroll 16
        for (int k = 0; k < DIM; k++){
            float4 a4 = *(const float4*)&f1T[k*STR + ty*4];
            float4 b4 = *(const float4*)&f2T[k*STR + tx*4];
            acc[0][0] += a4.x*b4.x; acc[0][1] += a4.x*b4.y;
            acc[0][2] += a4.x*b4.z; acc[0][3] += a4.x*b4.w;
            acc[1][0] += a4.y*b4.x; acc[1][1] += a4.y*b4.y;
            acc[1][2] += a4.y*b4.z; acc[1][3] += a4.y*b4.w;
            acc[2][0] += a4.z*b4.x; acc[2][1] += a4.z*b4.y;
            acc[2][2] += a4.z*b4.z; acc[2][3] += a4.z*b4.w;
            acc[3][0] += a4.w*b4.x; acc[3][1] += a4.w*b4.y;
            acc[3][2] += a4.w*b4.z; acc[3][3] += a4.w*b4.w;
        }

        // spatial coordinates of my 4 cols
        float xj[3][4];
        #pragma unroll
        for (int c = 0; c < 3; c++){
            float4 v = *(const float4*)&p2T[c*STR + tx*4];
            xj[c][0] = v.x; xj[c][1] = v.y; xj[c][2] = v.z; xj[c][3] = v.w;
        }

        // epilogue: per-row online update (one rescale per tile per row)
        #pragma unroll
        for (int r = 0; r < 4; r++){
            float s1v[4], s2v[4];
            #pragma unroll
            for (int q = 0; q < 4; q++){
                s2v[q] = fminf(acc[r][q], 0.0f);       // clamp d2 >= 0
                float t0 = xi[r][0] - xj[0][q];
                float t1 = xi[r][1] - xj[1][q];
                float t2 = xi[r][2] - xj[2][q];
                s1v[q] = -(t0*t0 + t1*t1 + t2*t2);     // exact >= 0 distance
            }
            float tm1 = fmaxf(fmaxf(s1v[0], s1v[1]), fmaxf(s1v[2], s1v[3]));
            float tm2 = fmaxf(fmaxf(s2v[0], s2v[1]), fmaxf(s2v[2], s2v[3]));
            float m1n = fmaxf(m1[r], tm1);
            float m2n = fmaxf(m2[r], tm2);
            float c1 = ex2(m1[r] - m1n);
            float c2 = ex2(m2[r] - m2n);
            float e1[4], e2[4];
            #pragma unroll
            for (int q = 0; q < 4; q++){
                e1[q] = ex2(s1v[q] - m1n);
                e2[q] = ex2(s2v[q] - m2n);
            }
            float sZ1 = (e1[0]+e1[1]) + (e1[2]+e1[3]);
            float sZ2 = (e2[0]+e2[1]) + (e2[2]+e2[3]);
            float sA  = (e1[0]*e1[0]+e1[1]*e1[1]) + (e1[2]*e1[2]+e1[3]*e1[3]);
            float sB  = (e2[0]*e2[0]+e2[1]*e2[1]) + (e2[2]*e2[2]+e2[3]*e2[3]);
            float sC  = (e1[0]*e2[0]+e1[1]*e2[1]) + (e1[2]*e2[2]+e1[3]*e2[3]);
            Z1[r] = Z1[r]*c1        + sZ1;
            Aa[r] = Aa[r]*(c1*c1)   + sA;
            Z2[r] = Z2[r]*c2        + sZ2;
            Bb[r] = Bb[r]*(c2*c2)   + sB;
            Cc[r] = Cc[r]*(c1*c2)   + sC;
            m1[r] = m1n; m2[r] = m2n;
        }
    }

    // ---- merge the 16 tx-lane partial states per row ----
    #pragma unroll
    for (int r = 0; r < 4; r++){
        #pragma unroll
        for (int off = 8; off >= 1; off >>= 1){
            float om1 = __shfl_xor_sync(0xffffffffu, m1[r], off);
            float om2 = __shfl_xor_sync(0xffffffffu, m2[r], off);
            float oZ1 = __shfl_xor_sync(0xffffffffu, Z1[r], off);
            float oZ2 = __shfl_xor_sync(0xffffffffu, Z2[r], off);
            float oA  = __shfl_xor_sync(0xffffffffu, Aa[r], off);
            float oB  = __shfl_xor_sync(0xffffffffu, Bb[r], off);
            float oC  = __shfl_xor_sync(0xffffffffu, Cc[r], off);
            float nm1 = fmaxf(m1[r], om1);
            float nm2 = fmaxf(m2[r], om2);
            float c1 = ex2(m1[r] - nm1), d1 = ex2(om1 - nm1);
            float c2 = ex2(m2[r] - nm2), d2 = ex2(om2 - nm2);
            Z1[r] = Z1[r]*c1      + oZ1*d1;
            Aa[r] = Aa[r]*c1*c1   + oA*d1*d1;
            Z2[r] = Z2[r]*c2      + oZ2*d2;
            Bb[r] = Bb[r]*c2*c2   + oB*d2*d2;
            Cc[r] = Cc[r]*(c1*c2) + oC*(d1*d2);
            m1[r] = nm1; m2[r] = nm2;
        }
    }

    // ---- loss per row, weighted sum over CTA ----
    if (tx == 0){
        float wacc = 0.0f;
        #pragma unroll
        for (int r = 0; r < 4; r++){
            float i1 = 1.0f / Z1[r];
            float i2 = 1.0f / Z2[r];
            float loss = Aa[r]*i1*i1 - 2.0f*Cc[r]*i1*i2 + Bb[r]*i2*i2;
            wacc += wts[b*NPTS + i0 + ty*4 + r] * loss;
        }
        sred[ty] = wacc;
    }
    __syncthreads();
    if (tid == 0){
        float s = 0.0f;
        #pragma unroll
        for (int t = 0; t < 16; t++) s += sred[t];
        g_partial[b*ITILES + blockIdx.x] = s;
    }
}

// ---------------------------------------------------------------------------
// Kernel 3: deterministic final reduction (64 partials per batch)
// ---------------------------------------------------------------------------
__global__ void reduce_kernel(float* __restrict__ out)
{
    int b    = threadIdx.x >> 5;    // 4 warps, one per batch
    int lane = threadIdx.x & 31;
    float s = g_partial[b*ITILES + lane] + g_partial[b*ITILES + 32 + lane];
    #pragma unroll
    for (int off = 16; off >= 1; off >>= 1)
        s += __shfl_xor_sync(0xffffffffu, s, off);
    if (lane == 0) out[b] = s;
}

// ---------------------------------------------------------------------------
extern "C" void kernel_launch(void* const* d_in, const int* in_sizes, int n_in,
                              void* d_out, int out_size)
{
    const float* pts = (const float*)d_in[0];  // [4,4096,3]
    const float* wts = (const float*)d_in[1];  // [4,4096]
    const float* f1  = (const float*)d_in[2];  // [4,4096,64]
    const float* f2  = (const float*)d_in[3];  // [4,4096,64]
    float* out = (float*)d_out;                // [4]

    norms_kernel<<<(BATCH*NPTS)/8, 256>>>(f1, f2);
    dim3 grid(ITILES, BATCH);
    loss_kernel<<<grid, 256>>>(pts, wts, f1, f2);
    reduce_kernel<<<1, 128>>>(out);
}

// round 3
// speedup vs baseline: 2.5574x; 2.5555x over previous
#include <cuda_runtime.h>
#include <cuda_bf16.h>
#include <cstdint>

#define BATCH 4
#define NPTS  4096
#define DIM   64
#define LOG2E 1.4426950408889634f
#define SC_F  24.0224478f          // sqrt(log2e)/0.05
#define TWOL  2.8853900817779268f  // 2*log2e

#define BM 128
#define BN 128
#define NJT (NPTS/BN)   // 32
#define NIT (NPTS/BM)   // 32

#define ROWB 272                    // 256B packed row + 16B pad
#define OFF_A 0
#define SZ_A  (128*ROWB)            // 34816
#define OFF_B (SZ_A)
#define SZ_BB (128*ROWB)
#define OFF_P (OFF_B + 2*SZ_BB)     // 104448
#define OFF_M (OFF_P + 2*128*16)    // 108544
#define OFF_R (OFF_M + 128*24)      // 111616
#define SMEM_TOTAL (OFF_R + 64)     // 111680

// scratch (no allocation allowed)
__device__ __align__(16) uint32_t g_pk1[BATCH*NPTS*64]; // [hi64|lo64] bf16, f1*2log2e
__device__ __align__(16) uint32_t g_pk2[BATCH*NPTS*64]; // [hi64|lo64] bf16, f2 raw
__device__ __align__(16) float4   g_pi[BATCH*NPTS];     // coords*SC
__device__ __align__(16) float4   g_pj[BATCH*NPTS];     // coords*SC, w = log2e*||f2||^2
__device__ float g_partial[BATCH*NIT];

__device__ __forceinline__ float ex2(float x){
    float y; asm("ex2.approx.ftz.f32 %0, %1;" : "=f"(y) : "f"(x)); return y;
}
__device__ __forceinline__ void cpa16(uint32_t dst, const void* src){
    asm volatile("cp.async.cg.shared.global [%0], [%1], 16;\n" :: "r"(dst), "l"(src));
}
__device__ __forceinline__ void ldmx4(uint32_t& r0,uint32_t& r1,uint32_t& r2,uint32_t& r3, uint32_t a){
    asm volatile("ldmatrix.sync.aligned.m8n8.x4.shared.b16 {%0,%1,%2,%3}, [%4];\n"
                 : "=r"(r0),"=r"(r1),"=r"(r2),"=r"(r3) : "r"(a));
}
__device__ __forceinline__ void mma16816(float* c, const uint32_t* a, uint32_t b0, uint32_t b1){
    asm volatile("mma.sync.aligned.m16n8k16.row.col.f32.bf16.bf16.f32 "
                 "{%0,%1,%2,%3}, {%4,%5,%6,%7}, {%8,%9}, {%0,%1,%2,%3};\n"
                 : "+f"(c[0]),"+f"(c[1]),"+f"(c[2]),"+f"(c[3])
                 : "r"(a[0]),"r"(a[1]),"r"(a[2]),"r"(a[3]), "r"(b0),"r"(b1));
}

// ---------------------------------------------------------------------------
__global__ void prep_kernel(const float* __restrict__ pts,
                            const float* __restrict__ f1,
                            const float* __restrict__ f2)
{
    int gw   = (blockIdx.x*blockDim.x + threadIdx.x) >> 5;
    int lane = threadIdx.x & 31;
    if (gw >= BATCH*NPTS) return;
    const float* r1 = f1 + (size_t)gw*DIM;
    const float* r2 = f2 + (size_t)gw*DIM;
    float a0 = r1[lane], a1 = r1[lane+32];
    float b0 = r2[lane], b1 = r2[lane+32];
    float n2 = b0*b0 + b1*b1;
    #pragma unroll
    for (int o=16;o>=1;o>>=1) n2 += __shfl_xor_sync(~0u,n2,o);

    float s0 = a0*TWOL, s1 = a1*TWOL;
    __nv_bfloat16 h0=__float2bfloat16(s0), h1=__float2bfloat16(s1);
    __nv_bfloat16 l0=__float2bfloat16(s0-__bfloat162float(h0));
    __nv_bfloat16 l1=__float2bfloat16(s1-__bfloat162float(h1));
    __nv_bfloat16* o1 = (__nv_bfloat16*)(g_pk1 + (size_t)gw*64);
    o1[lane]=h0; o1[32+lane]=h1; o1[64+lane]=l0; o1[96+lane]=l1;

    __nv_bfloat16 H0=__float2bfloat16(b0), H1=__float2bfloat16(b1);
    __nv_bfloat16 L0=__float2bfloat16(b0-__bfloat162float(H0));
    __nv_bfloat16 L1=__float2bfloat16(b1-__bfloat162float(H1));
    __nv_bfloat16* o2 = (__nv_bfloat16*)(g_pk2 + (size_t)gw*64);
    o2[lane]=H0; o2[32+lane]=H1; o2[64+lane]=L0; o2[96+lane]=L1;

    if (lane==0){
        float px = pts[(size_t)gw*3+0]*SC_F;
        float py = pts[(size_t)gw*3+1]*SC_F;
        float pz = pts[(size_t)gw*3+2]*SC_F;
        g_pi[gw] = make_float4(px,py,pz,0.0f);
        g_pj[gw] = make_float4(px,py,pz,n2*LOG2E);
    }
}

// ---------------------------------------------------------------------------
// 256 threads = 8 warps (wy 0..3 x wx 0..1); warp tile 32 rows x 64 cols.
// ---------------------------------------------------------------------------
__global__ __launch_bounds__(256,1)
void loss_kernel(const float* __restrict__ wts)
{
    extern __shared__ __align__(16) char smem[];
    const uint32_t sb = (uint32_t)__cvta_generic_to_shared(smem);
    const int b  = blockIdx.y;
    const int i0 = blockIdx.x*BM;
    const int tid = threadIdx.x;
    const int w = tid>>5, lane = tid&31;
    const int wy = w>>1, wx = w&1;
    const int g = lane>>2, tig = lane&3;

    // A tile + first B tile + P via cp.async
    {
        const char* gA = (const char*)(g_pk1 + (size_t)(b*NPTS+i0)*64);
        const char* gB = (const char*)(g_pk2 + (size_t)(b*NPTS)*64);
        #pragma unroll
        for(int q=0;q<8;q++){
            int idx=q*256+tid, r=idx>>4, c=idx&15;
            cpa16(sb + OFF_A + r*ROWB + c*16, gA + r*256 + c*16);
            cpa16(sb + OFF_B + r*ROWB + c*16, gB + r*256 + c*16);
        }
        if (tid<128) cpa16(sb + OFF_P + tid*16, (const char*)(g_pj + b*NPTS + tid));
        asm volatile("cp.async.commit_group;\n");
    }

    // ldmatrix lane address components
    const uint32_t aAddr = sb + OFF_A + (wy*32 + (lane&15))*ROWB + (lane>>4)*16;
    const int bn_row = (lane&7) + (((lane>>4)&1)<<3);
    const uint32_t bk16 = ((lane>>3)&1)*16;

    float xix[4],xiy[4],xiz[4]; int rl_[4];
    #pragma unroll
    for(int si=0;si<4;si++){
        int mb=si>>1, rp=si&1;
        int rl = wy*32 + mb*16 + rp*8 + g;
        rl_[si]=rl;
        float4 v = g_pi[b*NPTS + i0 + rl];
        xix[si]=v.x; xiy[si]=v.y; xiz[si]=v.z;
    }
    float m2s[4],Z1s[4],Z2s[4],As[4],Bs[4],Cs[4];
    #pragma unroll
    for(int si=0;si<4;si++){ m2s[si]=-3.0e38f; Z1s[si]=0.f;Z2s[si]=0.f;As[si]=0.f;Bs[si]=0.f;Cs[si]=0.f; }

    for(int jt=0; jt<NJT; jt++){
        const int buf = jt&1;
        asm volatile("cp.async.wait_group 0;\n" ::: "memory");
        __syncthreads();
        if (jt+1 < NJT){
            const int nb_ = buf^1;
            const char* gB = (const char*)(g_pk2 + (size_t)(b*NPTS + (jt+1)*BN)*64);
            #pragma unroll
            for(int q=0;q<8;q++){
                int idx=q*256+tid, r=idx>>4, c=idx&15;
                cpa16(sb + OFF_B + nb_*SZ_BB + r*ROWB + c*16, gB + r*256 + c*16);
            }
            if (tid<128) cpa16(sb + OFF_P + nb_*2048 + tid*16,
                               (const char*)(g_pj + b*NPTS + (jt+1)*BN + tid));
            asm volatile("cp.async.commit_group;\n");
        }

        // ---- MMA: 12 k-chunks = HH(4) + HL(4) + LH(4) ----
        float acc[2][8][4];
        #pragma unroll
        for(int mb=0;mb<2;mb++)
            #pragma unroll
            for(int nb=0;nb<8;nb++)
                #pragma unroll
                for(int q=0;q<4;q++) acc[mb][nb][q]=0.f;

        const uint32_t pB = sb + OFF_B + buf*SZ_BB;
        #pragma unroll
        for(int kb=0;kb<12;kb++){
            const int offA = ((kb&3)<<5) + ((kb>=8)?128:0);
            const int offB = (kb<4)? (kb<<5) : ((kb<8)? (128+((kb-4)<<5)) : ((kb-8)<<5));
            uint32_t a[2][4];
            ldmx4(a[0][0],a[0][1],a[0][2],a[0][3], aAddr + offA);
            ldmx4(a[1][0],a[1][1],a[1][2],a[1][3], aAddr + 16*ROWB + offA);
            uint32_t bb[4][4];
            #pragma unroll
            for(int n2=0;n2<4;n2++)
                ldmx4(bb[n2][0],bb[n2][1],bb[n2][2],bb[n2][3],
                      pB + (wx*64 + n2*16 + bn_row)*ROWB + bk16 + offB);
            #pragma unroll
            for(int mb=0;mb<2;mb++)
                #pragma unroll
                for(int n2=0;n2<4;n2++){
                    mma16816(acc[mb][n2*2  ], a[mb], bb[n2][0], bb[n2][1]);
                    mma16816(acc[mb][n2*2+1], a[mb], bb[n2][2], bb[n2][3]);
                }
        }

        // ---- epilogue ----
        const float*  pW = (const float*)(smem + OFF_P + buf*2048);
        const float4* pP = (const float4*)(smem + OFF_P + buf*2048);

        // per-thread min of cn2 over my 16 cols
        float mn = 3.0e38f;
        #pragma unroll
        for(int nb=0;nb<8;nb++){
            int c0 = wx*64 + nb*8 + tig*2;
            mn = fminf(mn, fminf(pW[c0*4+3], pW[(c0+1)*4+3]));
        }
        // per-row rescale with upper-bound max
        #pragma unroll
        for(int si=0;si<4;si++){
            int mb=si>>1, rp=si&1;
            float mx = -3.0e38f;
            #pragma unroll
            for(int nb=0;nb<8;nb++)
                mx = fmaxf(mx, fmaxf(acc[mb][nb][rp*2], acc[mb][nb][rp*2+1]));
            float cand = mx - mn;
            float m2n = fmaxf(m2s[si], cand);
            float c2 = ex2(m2s[si] - m2n);
            Z2s[si]*=c2; Cs[si]*=c2; Bs[si]*=c2*c2; m2s[si]=m2n;
        }
        // accumulate
        #pragma unroll
        for(int nb=0;nb<8;nb++){
            #pragma unroll
            for(int qq=0;qq<2;qq++){
                int c = wx*64 + nb*8 + tig*2 + qq;
                float4 v = pP[c];
                #pragma unroll
                for(int si=0;si<4;si++){
                    int mb=si>>1, rp=si&1;
                    float s2 = acc[mb][nb][rp*2+qq] - v.w;
                    float e2 = ex2(s2 - m2s[si]);
                    float dx = xix[si]-v.x, dy = xiy[si]-v.y, dz = xiz[si]-v.z;
                    float t = dx*-dx; t = fmaf(dy,-dy,t); t = fmaf(dz,-dz,t);
                    float e1 = ex2(t);
                    Z1s[si]+=e1; As[si]=fmaf(e1,e1,As[si]);
                    Z2s[si]+=e2; Bs[si]=fmaf(e2,e2,Bs[si]);
                    Cs[si]=fmaf(e1,e2,Cs[si]);
                }
            }
        }
    }

    // ---- merge 4 tig-lanes per row ----
    #pragma unroll
    for(int si=0;si<4;si++){
        #pragma unroll
        for(int off=1; off<=2; off<<=1){
            float om = __shfl_xor_sync(~0u, m2s[si], off);
            float oZ2= __shfl_xor_sync(~0u, Z2s[si], off);
            float oB = __shfl_xor_sync(~0u, Bs[si], off);
            float oC = __shfl_xor_sync(~0u, Cs[si], off);
            float oZ1= __shfl_xor_sync(~0u, Z1s[si], off);
            float oA = __shfl_xor_sync(~0u, As[si], off);
            float nm = fmaxf(m2s[si], om);
            float c = ex2(m2s[si]-nm), d = ex2(om-nm);
            Z2s[si]=Z2s[si]*c + oZ2*d;
            Bs[si]=Bs[si]*c*c + oB*d*d;
            Cs[si]=Cs[si]*c + oC*d;
            Z1s[si]+=oZ1; As[si]+=oA;
            m2s[si]=nm;
        }
    }
    // ---- merge wx pair via smem ----
    float* sM = (float*)(smem + OFF_M);
    float* sR = (float*)(smem + OFF_R);
    if (wx==1 && tig==0){
        #pragma unroll
        for(int si=0;si<4;si++){
            float* p = sM + rl_[si]*6;
            p[0]=m2s[si]; p[1]=Z2s[si]; p[2]=Bs[si]; p[3]=Cs[si]; p[4]=Z1s[si]; p[5]=As[si];
        }
    }
    __syncthreads();
    float wacc = 0.0f;
    if (wx==0 && tig==0){
        #pragma unroll
        for(int si=0;si<4;si++){
            const float* p = sM + rl_[si]*6;
            float om=p[0], oZ2=p[1], oB=p[2], oC=p[3], oZ1=p[4], oA=p[5];
            float nm = fmaxf(m2s[si], om);
            float c = ex2(m2s[si]-nm), d = ex2(om-nm);
            float Z2 = Z2s[si]*c + oZ2*d;
            float Bv = Bs[si]*c*c + oB*d*d;
            float Cv = Cs[si]*c + oC*d;
            float Z1 = Z1s[si] + oZ1;
            float Av = As[si] + oA;
            float i1 = 1.0f/Z1, i2 = 1.0f/Z2;
            float loss = Av*i1*i1 - 2.0f*Cv*i1*i2 + Bv*i2*i2;
            wacc += wts[b*NPTS + i0 + rl_[si]] * loss;
        }
    }
    #pragma unroll
    for(int off=16; off>=1; off>>=1) wacc += __shfl_xor_sync(~0u, wacc, off);
    if (wx==0 && lane==0) sR[wy] = wacc;
    __syncthreads();
    if (tid==0)
        g_partial[b*NIT + blockIdx.x] = (sR[0]+sR[1]) + (sR[2]+sR[3]);
}

// ---------------------------------------------------------------------------
__global__ void reduce_kernel(float* __restrict__ out)
{
    int b    = threadIdx.x >> 5;
    int lane = threadIdx.x & 31;
    float s = g_partial[b*NIT + lane];
    #pragma unroll
    for(int off=16; off>=1; off>>=1) s += __shfl_xor_sync(~0u, s, off);
    if (lane==0) out[b] = s;
}

// ---------------------------------------------------------------------------
extern "C" void kernel_launch(void* const* d_in, const int* in_sizes, int n_in,
                              void* d_out, int out_size)
{
    const float* pts = (const float*)d_in[0];
    const float* wts = (const float*)d_in[1];
    const float* f1  = (const float*)d_in[2];
    const float* f2  = (const float*)d_in[3];
    float* out = (float*)d_out;

    cudaFuncSetAttribute(loss_kernel, cudaFuncAttributeMaxDynamicSharedMemorySize, SMEM_TOTAL);
    prep_kernel<<<(BATCH*NPTS)/8, 256>>>(pts, f1, f2);
    dim3 grid(NIT, BATCH);
    loss_kernel<<<grid, 256, SMEM_TOTAL>>>(wts);
    reduce_kernel<<<1, 128>>>(out);
}